// round 1
// baseline (speedup 1.0000x reference)
#include <cuda_runtime.h>
#include <math.h>

// Problem dims (compile-time)
#define Tn   4
#define Bn   32
#define Cn   384
#define HFn  1536
#define Hn   14
#define Wn   14
#define HWn  196
#define En   8
#define Nn   128          // T*B
#define OUT_MAIN (Nn*Cn*HWn)

// ---------------- device scratch (static; no allocations) ----------------
__device__ float g_w1t[En*Cn*HFn];   // [e][c][o]  (transposed w1)
__device__ float g_w2t[En*HFn*Cn];   // [e][hf][co] (transposed w2)
__device__ float g_inv1[En*HFn];     // BN1 scale
__device__ float g_q1[En*HFn];       // BN1 shift - tau  (spike2: inv1*h + q1 >= 0)
__device__ float g_colmax[En*Cn];    // max_o w1[o,c]
__device__ float g_thrmin[En];       // min_o (tau - sh1)/inv1  (valid when canskip)
__device__ int   g_canskip[En];      // all inv1 > 0
__device__ float g_m2c[En*Cn];       // BN2 scale
__device__ float g_a2c[En*Cn];       // inv2*b2 + (be2 - m2*inv2)
__device__ float g_invr[En];
__device__ float g_shr[En];
__device__ float g_sbar[Nn*Cn];      // spatial-mean router spikes
__device__ float g_logits[Nn*En];
__device__ int   g_sel[Nn*2];
__device__ float g_gate[Nn*2];

// ---------------- prep: transposes ----------------
__global__ void k_transpose_w1(const float* __restrict__ in){ // in: [E][HF][C] -> g_w1t [E][C][HF]
  __shared__ float tile[32][33];
  int e = blockIdx.z;
  const float* src = in + (size_t)e*HFn*Cn;
  float* dst = g_w1t + (size_t)e*Cn*HFn;
  int c0 = blockIdx.x*32, r0 = blockIdx.y*32;  // c over Cn, r over HFn
  #pragma unroll
  for (int j=0;j<32;j+=8)
    tile[threadIdx.y+j][threadIdx.x] = src[(size_t)(r0+threadIdx.y+j)*Cn + (c0+threadIdx.x)];
  __syncthreads();
  #pragma unroll
  for (int j=0;j<32;j+=8)
    dst[(size_t)(c0+threadIdx.y+j)*HFn + (r0+threadIdx.x)] = tile[threadIdx.x][threadIdx.y+j];
}

__global__ void k_transpose_w2(const float* __restrict__ in){ // in: [E][C][HF] -> g_w2t [E][HF][C]
  __shared__ float tile[32][33];
  int e = blockIdx.z;
  const float* src = in + (size_t)e*Cn*HFn;
  float* dst = g_w2t + (size_t)e*HFn*Cn;
  int c0 = blockIdx.x*32, r0 = blockIdx.y*32;  // c over HFn, r over Cn
  #pragma unroll
  for (int j=0;j<32;j+=8)
    tile[threadIdx.y+j][threadIdx.x] = src[(size_t)(r0+threadIdx.y+j)*HFn + (c0+threadIdx.x)];
  __syncthreads();
  #pragma unroll
  for (int j=0;j<32;j+=8)
    dst[(size_t)(c0+threadIdx.y+j)*Cn + (r0+threadIdx.x)] = tile[threadIdx.x][threadIdx.y+j];
}

// colmax over g_w1t: one warp per (e,c)
__global__ void k_colmax(){
  int gw = (blockIdx.x*blockDim.x + threadIdx.x) >> 5;
  int lane = threadIdx.x & 31;
  if (gw >= En*Cn) return;
  const float* col = g_w1t + (size_t)gw*HFn;
  float m = -1e30f;
  for (int o=lane;o<HFn;o+=32) m = fmaxf(m, col[o]);
  #pragma unroll
  for (int d=16;d>=1;d>>=1) m = fmaxf(m, __shfl_xor_sync(0xffffffffu, m, d));
  if (lane==0) g_colmax[gw] = m;
}

__global__ void k_prep_l1(const float* __restrict__ g1,const float* __restrict__ be1,
                          const float* __restrict__ m1,const float* __restrict__ v1,
                          const float* __restrict__ taus){
  int e = blockIdx.x;
  float tau = taus[e];
  __shared__ float smin[512];
  float lmin = 1e30f; bool ok = true;
  for (int o=threadIdx.x;o<HFn;o+=512){
    float inv = g1[e*HFn+o] / sqrtf(v1[e*HFn+o] + 1e-5f);
    float sh  = be1[e*HFn+o] - m1[e*HFn+o]*inv;
    g_inv1[e*HFn+o] = inv;
    g_q1[e*HFn+o]   = sh - tau;
    if (inv > 0.0f) lmin = fminf(lmin, (tau - sh)/inv);
    else ok = false;
  }
  smin[threadIdx.x] = lmin;
  int okc = __syncthreads_count(ok);   // also acts as barrier
  for (int s=256;s>=1;s>>=1){
    if (threadIdx.x<s) smin[threadIdx.x] = fminf(smin[threadIdx.x], smin[threadIdx.x+s]);
    __syncthreads();
  }
  if (threadIdx.x==0){ g_thrmin[e]=smin[0]; g_canskip[e]=(okc==512); }
}

__global__ void k_prep_l2(const float* __restrict__ g2,const float* __restrict__ be2,
                          const float* __restrict__ m2,const float* __restrict__ v2,
                          const float* __restrict__ b2){
  int e = blockIdx.x, c = threadIdx.x;
  float inv = g2[e*Cn+c] / sqrtf(v2[e*Cn+c] + 1e-5f);
  float sh  = be2[e*Cn+c] - m2[e*Cn+c]*inv;
  g_m2c[e*Cn+c] = inv;
  g_a2c[e*Cn+c] = inv*b2[e*Cn+c] + sh;
}

__global__ void k_prep_router(const float* __restrict__ rg,const float* __restrict__ rbeta,
                              const float* __restrict__ rmean,const float* __restrict__ rvar){
  int e = threadIdx.x;
  if (e < En){
    float inv = rg[e] / sqrtf(rvar[e] + 1e-5f);
    g_invr[e] = inv;
    g_shr[e]  = rbeta[e] - rmean[e]*inv;
  }
}

// ---------------- router: LIF (tau=2) + spatial-mean spikes ----------------
__global__ void k_lif(const float* __restrict__ x){
  int bc = blockIdx.x;                   // b*Cn + c
  int b = bc / Cn, c = bc % Cn;
  int p = threadIdx.x;                   // 0..195
  float v = 0.0f; int cnt[Tn];
  #pragma unroll
  for (int t=0;t<Tn;t++){
    float xv = x[((size_t)((t*Bn+b)*Cn + c))*HWn + p];
    v += (xv - v)*0.5f;
    bool s = (v - 1.0f) >= 0.0f;
    cnt[t] = __syncthreads_count(s);
    if (s) v = 0.0f;
  }
  if (p==0){
    #pragma unroll
    for (int t=0;t<Tn;t++)
      g_sbar[(t*Bn+b)*Cn + c] = (float)cnt[t] / (float)HWn;
  }
}

__global__ void k_logits(const float* __restrict__ rw, const float* __restrict__ rb){
  int n = blockIdx.x;
  int e = threadIdx.x >> 5, lane = threadIdx.x & 31;  // 256 thr = 8 warps
  float dot = 0.0f;
  for (int c=lane;c<Cn;c+=32) dot += g_sbar[n*Cn+c]*rw[e*Cn+c];
  #pragma unroll
  for (int d=16;d>=1;d>>=1) dot += __shfl_xor_sync(0xffffffffu, dot, d);
  if (lane==0) g_logits[n*En+e] = g_invr[e]*(dot + rb[e]) + g_shr[e];
}

// softmax + top2 + gate + aux loss. One block, Nn threads.
__global__ void k_gate(float* __restrict__ auxout){
  int n = threadIdx.x;
  float lg[En];
  #pragma unroll
  for (int e=0;e<En;e++) lg[e] = g_logits[n*En+e];
  float mx = lg[0];
  #pragma unroll
  for (int e=1;e<En;e++) mx = fmaxf(mx, lg[e]);
  float pe[En]; float sum = 0.0f;
  #pragma unroll
  for (int e=0;e<En;e++){ pe[e] = expf(lg[e]-mx); sum += pe[e]; }
  #pragma unroll
  for (int e=0;e<En;e++) pe[e] /= sum;
  int i1 = 0; float p1 = pe[0];
  #pragma unroll
  for (int e=1;e<En;e++) if (pe[e] > p1){ p1 = pe[e]; i1 = e; }
  int i2 = -1; float p2 = -1.0f;
  #pragma unroll
  for (int e=0;e<En;e++) if (e != i1 && pe[e] > p2){ p2 = pe[e]; i2 = e; }
  float ws = p1 + p2;
  g_sel[n*2]   = i1;  g_sel[n*2+1]  = i2;
  g_gate[n*2]  = p1/ws; g_gate[n*2+1] = p2/ws;

  // aux = 0.01 * E * sum_e f_e * p_e
  __shared__ float sp[Nn];
  float fp = 0.0f;
  for (int e=0;e<En;e++){
    int cnt = __syncthreads_count(i1==e || i2==e);
    sp[n] = pe[e];
    __syncthreads();
    for (int s=64;s>=1;s>>=1){ if (n<s) sp[n]+=sp[n+s]; __syncthreads(); }
    if (n==0) fp += ((float)cnt/(float)Nn) * (sp[0]/(float)Nn);
    __syncthreads();
  }
  if (n==0 && auxout) auxout[0] = 0.01f * (float)En * fp;
}

// ---------------- main expert kernel: one block per (pixel, token) ----------------
__global__ void __launch_bounds__(Cn) k_expert(const float* __restrict__ x,
                                               const float* __restrict__ taus,
                                               float* __restrict__ out){
  int p = blockIdx.x;       // 0..195
  int n = blockIdx.y;       // 0..127
  int tid = threadIdx.x;    // 0..383 == channel c
  int lane = tid & 31, wid = tid >> 5;

  __shared__ int   s_act[Cn];
  __shared__ short s_act2[HFn];
  __shared__ float s_red[Cn];
  __shared__ int   s_wc[12], s_wo[12];
  __shared__ int   s_cnt, s_cnt2;

  float xv = x[((size_t)(n*Cn + tid))*HWn + p];
  int   e0 = g_sel[n*2],  e1 = g_sel[n*2+1];
  float gg0 = g_gate[n*2], gg1 = g_gate[n*2+1];
  float result = xv * (gg0 + gg1);   // residual appears inside every selected expert

  for (int k=0;k<2;k++){
    int   e = k ? e1 : e0;
    float g = k ? gg1 : gg0;
    float tau = taus[e];
    bool cond = (xv/tau - 1.0f) >= 0.0f;   // layer-1 spike (exact reference form)

    // deterministic compaction of active channels + sound upper bound on h
    unsigned m = __ballot_sync(0xffffffffu, cond);
    if (lane==0) s_wc[wid] = __popc(m);
    s_red[tid] = cond ? g_colmax[e*Cn+tid] : 0.0f;
    __syncthreads();
    if (tid==0){ int s=0; for (int w=0;w<12;w++){ s_wo[w]=s; s+=s_wc[w]; } s_cnt=s; }
    __syncthreads();
    if (cond) s_act[s_wo[wid] + __popc(m & ((1u<<lane)-1u))] = tid;
    if (tid < 128) s_red[tid] += s_red[tid+256];
    __syncthreads();
    for (int s=128;s>=1;s>>=1){ if (tid<s) s_red[tid]+=s_red[tid+s]; __syncthreads(); }

    int   cnt = s_cnt;
    float ub  = s_red[0];
    bool  skip = g_canskip[e] && (ub < g_thrmin[e] - 1e-3f);  // proves s2 == all-zero

    if (!skip){
      // h[o] = sum over active c of w1t[e][c][o]; each thread owns o = 4*tid..4*tid+3
      float4 h = make_float4(0.f,0.f,0.f,0.f);
      const float* wbase = g_w1t + (size_t)e*Cn*HFn;
      int i = 0;
      for (; i+4<=cnt; i+=4){
        float4 a0 = ((const float4*)(wbase + (size_t)s_act[i  ]*HFn))[tid];
        float4 a1 = ((const float4*)(wbase + (size_t)s_act[i+1]*HFn))[tid];
        float4 a2 = ((const float4*)(wbase + (size_t)s_act[i+2]*HFn))[tid];
        float4 a3 = ((const float4*)(wbase + (size_t)s_act[i+3]*HFn))[tid];
        h.x += (a0.x+a1.x)+(a2.x+a3.x);
        h.y += (a0.y+a1.y)+(a2.y+a3.y);
        h.z += (a0.z+a1.z)+(a2.z+a3.z);
        h.w += (a0.w+a1.w)+(a2.w+a3.w);
      }
      for (; i<cnt; i++){
        float4 a = ((const float4*)(wbase + (size_t)s_act[i]*HFn))[tid];
        h.x += a.x; h.y += a.y; h.z += a.z; h.w += a.w;
      }
      // layer-2 spikes: inv1*h + (sh1 - tau) >= 0  (handles any BN sign exactly)
      bool fire[4]; int fcnt = 0;
      float hv[4] = {h.x, h.y, h.z, h.w};
      #pragma unroll
      for (int j=0;j<4;j++){
        int o = tid*4 + j;
        fire[j] = fmaf(g_inv1[e*HFn+o], hv[j], g_q1[e*HFn+o]) >= 0.0f;
        fcnt += fire[j] ? 1 : 0;
      }
      // deterministic warp-scan compaction of fired o's
      int incl = fcnt;
      #pragma unroll
      for (int d=1; d<32; d<<=1){
        int u = __shfl_up_sync(0xffffffffu, incl, d);
        if (lane >= d) incl += u;
      }
      if (lane==31) s_wc[wid] = incl;
      __syncthreads();
      if (tid==0){ int s=0; for (int w=0;w<12;w++){ s_wo[w]=s; s+=s_wc[w]; } s_cnt2=s; }
      __syncthreads();
      int pos = s_wo[wid] + incl - fcnt;
      #pragma unroll
      for (int j=0;j<4;j++) if (fire[j]) s_act2[pos++] = (short)(tid*4 + j);
    } else {
      if (tid==0) s_cnt2 = 0;
    }
    __syncthreads();

    // layer-2 gather: a = sum over fired o of w2t[e][o][c]
    int cnt2 = s_cnt2;
    float a = 0.0f;
    const float* w2base = g_w2t + (size_t)e*HFn*Cn + tid;
    for (int i=0;i<cnt2;i++) a += w2base[(int)s_act2[i]*Cn];
    float val = fmaf(g_m2c[e*Cn+tid], a, g_a2c[e*Cn+tid]);  // BN2(conv+b2) folded
    result += g * val;
    __syncthreads();   // shared reused by next k
  }

  out[((size_t)(n*Cn + tid))*HWn + p] = result;
}

// ---------------- launch ----------------
extern "C" void kernel_launch(void* const* d_in, const int* in_sizes, int n_in,
                              void* d_out, int out_size){
  const float* x      = (const float*)d_in[0];
  const float* rw     = (const float*)d_in[1];
  const float* rb     = (const float*)d_in[2];
  const float* rgam   = (const float*)d_in[3];
  const float* rbeta  = (const float*)d_in[4];
  const float* rmean  = (const float*)d_in[5];
  const float* rvar   = (const float*)d_in[6];
  const float* w1     = (const float*)d_in[7];
  const float* b1     = (const float*)d_in[8];   (void)b1; // folded via q1? NOTE: b1 is zeros in setup but fold anyway below
  const float* g1     = (const float*)d_in[9];
  const float* be1    = (const float*)d_in[10];
  const float* m1     = (const float*)d_in[11];
  const float* v1     = (const float*)d_in[12];
  const float* w2     = (const float*)d_in[13];
  const float* b2     = (const float*)d_in[14];
  const float* g2     = (const float*)d_in[15];
  const float* be2    = (const float*)d_in[16];
  const float* m2     = (const float*)d_in[17];
  const float* v2     = (const float*)d_in[18];
  const float* taus   = (const float*)d_in[19];
  float* out = (float*)d_out;
  (void)in_sizes; (void)n_in;

  dim3 tb(32,8);
  k_transpose_w1<<<dim3(Cn/32, HFn/32, En), tb>>>(w1);
  k_transpose_w2<<<dim3(HFn/32, Cn/32, En), tb>>>(w2);
  k_colmax<<<(En*Cn*32 + 255)/256, 256>>>();
  k_prep_l1<<<En, 512>>>(g1, be1, m1, v1, taus);
  k_prep_l2<<<En, Cn>>>(g2, be2, m2, v2, b2);
  k_prep_router<<<1, 32>>>(rgam, rbeta, rmean, rvar);
  k_lif<<<Bn*Cn, HWn>>>(x);
  k_logits<<<Nn, 256>>>(rw, rb);
  float* auxp = (out_size > OUT_MAIN) ? (out + OUT_MAIN) : nullptr;
  k_gate<<<1, Nn>>>(auxp);
  k_expert<<<dim3(HWn, Nn), Cn>>>(x, taus, out);
}

// round 2
// speedup vs baseline: 1.1032x; 1.1032x over previous
#include <cuda_runtime.h>
#include <math.h>

#define Tn   4
#define Bn   32
#define Cn   384
#define HFn  1536
#define HWn  196
#define En   8
#define Nn   128
#define OUT_MAIN (Nn*Cn*HWn)
#define NG   32          // o-groups per expert
#define GSZ  48          // outputs per group (32*48 = 1536)
#define Pt   7           // pixels per expert block (7*28 = 196)

// ---------------- device scratch ----------------
__device__ float g_colmax32[En*Cn*NG];  // [e][c][g] = max_{o in g} w1[e][o][c]
__device__ float g_thrmin32[En*NG];     // min conv-threshold per group; -1e30 if group can't use bound
__device__ float g_sbar[Nn*Cn];
__device__ float g_logits[Nn*En];
__device__ int   g_sel[Nn*2];
__device__ float g_gate[Nn*2];

// ---------------- prep ----------------
__global__ void k_colmax32(const float* __restrict__ w1){
  int g = blockIdx.x, e = blockIdx.y, c = threadIdx.x;   // 384 threads
  const float* base = w1 + ((size_t)e*HFn + g*GSZ)*Cn + c;
  float m = -1e30f;
  #pragma unroll 8
  for (int o=0;o<GSZ;o++) m = fmaxf(m, base[(size_t)o*Cn]);
  g_colmax32[((size_t)e*Cn + c)*NG + g] = m;
}

__global__ void k_prep_groups(const float* __restrict__ g1,const float* __restrict__ be1,
                              const float* __restrict__ m1,const float* __restrict__ v1,
                              const float* __restrict__ b1,const float* __restrict__ taus){
  int g = blockIdx.x, e = blockIdx.y, j = threadIdx.x;   // 48 threads
  int o = g*GSZ + j;
  float tau = taus[e];
  float iv = g1[e*HFn+o] / sqrtf(v1[e*HFn+o] + 1e-5f);
  float sh = be1[e*HFn+o] - m1[e*HFn+o]*iv;
  bool ok = iv > 0.0f;
  float t = ok ? ((tau - sh)/iv - b1[e*HFn+o]) : 1e30f;   // conv-domain threshold
  __shared__ float sm[64];
  if (j < 16) sm[GSZ + j] = 1e30f;
  sm[j] = t;
  int okc = __syncthreads_count(ok);
  for (int s=32;s>=1;s>>=1){
    if (j < s) sm[j] = fminf(sm[j], sm[j+s]);
    __syncthreads();
  }
  if (j==0) g_thrmin32[e*NG + g] = (okc == GSZ) ? sm[0] : -1e30f;
}

// ---------------- router ----------------
__global__ void k_lif(const float* __restrict__ x){
  int bc = blockIdx.x;                   // b*Cn + c
  int b = bc / Cn, c = bc % Cn;
  int p = threadIdx.x;                   // 0..195
  float v = 0.0f; int cnt[Tn];
  #pragma unroll
  for (int t=0;t<Tn;t++){
    float xv = x[((size_t)((t*Bn+b)*Cn + c))*HWn + p];
    v += (xv - v)*0.5f;
    bool s = (v - 1.0f) >= 0.0f;
    cnt[t] = __syncthreads_count(s);
    if (s) v = 0.0f;
  }
  if (p==0){
    #pragma unroll
    for (int t=0;t<Tn;t++)
      g_sbar[(t*Bn+b)*Cn + c] = (float)cnt[t] / (float)HWn;
  }
}

__global__ void k_logits(const float* __restrict__ rw, const float* __restrict__ rb,
                         const float* __restrict__ rg, const float* __restrict__ rbeta,
                         const float* __restrict__ rmean, const float* __restrict__ rvar){
  int n = blockIdx.x;
  int e = threadIdx.x >> 5, lane = threadIdx.x & 31;  // 256 threads = 8 warps
  float dot = 0.0f;
  for (int c=lane;c<Cn;c+=32) dot += g_sbar[n*Cn+c]*rw[e*Cn+c];
  #pragma unroll
  for (int d=16;d>=1;d>>=1) dot += __shfl_xor_sync(0xffffffffu, dot, d);
  if (lane==0){
    float inv = rg[e] / sqrtf(rvar[e] + 1e-5f);
    g_logits[n*En+e] = inv*(dot + rb[e]) + (rbeta[e] - rmean[e]*inv);
  }
}

__global__ void k_gate(float* __restrict__ auxout){
  int n = threadIdx.x;
  float lg[En];
  #pragma unroll
  for (int e=0;e<En;e++) lg[e] = g_logits[n*En+e];
  float mx = lg[0];
  #pragma unroll
  for (int e=1;e<En;e++) mx = fmaxf(mx, lg[e]);
  float pe[En]; float sum = 0.0f;
  #pragma unroll
  for (int e=0;e<En;e++){ pe[e] = expf(lg[e]-mx); sum += pe[e]; }
  #pragma unroll
  for (int e=0;e<En;e++) pe[e] /= sum;
  int i1 = 0; float p1 = pe[0];
  #pragma unroll
  for (int e=1;e<En;e++) if (pe[e] > p1){ p1 = pe[e]; i1 = e; }
  int i2 = -1; float p2 = -1.0f;
  #pragma unroll
  for (int e=0;e<En;e++) if (e != i1 && pe[e] > p2){ p2 = pe[e]; i2 = e; }
  float ws = p1 + p2;
  g_sel[n*2]   = i1;  g_sel[n*2+1]  = i2;
  g_gate[n*2]  = p1/ws; g_gate[n*2+1] = p2/ws;

  __shared__ float sp[Nn];
  float fp = 0.0f;
  for (int e=0;e<En;e++){
    int cnt = __syncthreads_count(i1==e || i2==e);
    sp[n] = pe[e];
    __syncthreads();
    for (int s=64;s>=1;s>>=1){ if (n<s) sp[n]+=sp[n+s]; __syncthreads(); }
    if (n==0) fp += ((float)cnt/(float)Nn) * (sp[0]/(float)Nn);
    __syncthreads();
  }
  if (n==0 && auxout) auxout[0] = 0.01f * (float)En * fp;
}

// ---------------- main expert kernel: block = (7 pixels, token) ----------------
__global__ void __launch_bounds__(Cn) k_expert(
    const float* __restrict__ x, const float* __restrict__ taus,
    const float* __restrict__ w1, const float* __restrict__ b1,
    const float* __restrict__ g1, const float* __restrict__ be1,
    const float* __restrict__ m1, const float* __restrict__ v1,
    const float* __restrict__ w2, const float* __restrict__ b2,
    const float* __restrict__ g2, const float* __restrict__ be2,
    const float* __restrict__ m2, const float* __restrict__ v2,
    float* __restrict__ out){
  int p0 = blockIdx.x * Pt;  // 28 tiles of 7 pixels
  int n  = blockIdx.y;
  int tid = threadIdx.x;     // channel c
  int lane = tid & 31, wid = tid >> 5;

  __shared__ int    s_act[Cn];
  __shared__ float  s_part[256];
  __shared__ float  s_h[Cn];
  __shared__ short  s_fired[HFn];
  __shared__ int    s_wc[12], s_wo[12];
  __shared__ int    s_cnt, s_cnt2;
  __shared__ unsigned s_fm, s_m0, s_m1;

  float xv[Pt], res[Pt];
  const float* xb = x + ((size_t)n*Cn + tid)*HWn + p0;
  #pragma unroll
  for (int j=0;j<Pt;j++) xv[j] = xb[j];

  int   e0  = g_sel[n*2],   e1  = g_sel[n*2+1];
  float gw0 = g_gate[n*2],  gw1 = g_gate[n*2+1];
  #pragma unroll
  for (int j=0;j<Pt;j++) res[j] = xv[j] * (gw0 + gw1);  // residual per selected expert

  for (int k=0;k<2;k++){
    int   e  = k ? e1  : e0;
    float gw = k ? gw1 : gw0;
    float tau = taus[e];
    // BN2 coefficients for this thread's output channel (folded with conv bias b2)
    float inv2 = g2[e*Cn+tid] / sqrtf(v2[e*Cn+tid] + 1e-5f);
    float add2 = inv2*b2[e*Cn+tid] + (be2[e*Cn+tid] - m2[e*Cn+tid]*inv2);

    for (int j=0;j<Pt;j++){
      bool cond = (xv[j]/tau - 1.0f) >= 0.0f;      // layer-1 spike, exact reference form
      unsigned m = __ballot_sync(0xffffffffu, cond);
      if (lane==0) s_wc[wid] = __popc(m);
      __syncthreads();
      if (tid==0){ int s=0; for (int w=0;w<12;w++){ s_wo[w]=s; s+=s_wc[w]; } s_cnt=s; }
      if (tid==1) s_cnt2 = 0;
      __syncthreads();
      if (cond) s_act[s_wo[wid] + __popc(m & ((1u<<lane)-1u))] = tid;
      __syncthreads();
      int cnt = s_cnt;

      // ---- coarse per-group upper bound: ub_g = sum_{active c} colmax32[c][g] ----
      if (tid < 256){
        int g = tid & 31, idx = tid >> 5;                 // 8 partial strips x 32 groups
        float pp = 0.0f;
        const float* cm = g_colmax32 + (size_t)e*Cn*NG + g;
        for (int i=idx;i<cnt;i+=8) pp += cm[(size_t)s_act[i]*NG];
        s_part[tid] = pp;
      }
      __syncthreads();
      if (tid < 128) s_part[tid] += s_part[tid+128];
      __syncthreads();
      if (tid < 64)  s_part[tid] += s_part[tid+64];
      __syncthreads();
      if (wid == 0){
        float ub = s_part[lane] + s_part[lane+32];
        bool fail = ub >= g_thrmin32[e*NG+lane] - 1e-3f;  // conservative margin
        unsigned fm = __ballot_sync(0xffffffffu, fail);
        if (lane==0) s_fm = fm;
      }
      __syncthreads();

      // ---- exact h for failing groups only (rare) ----
      unsigned fm = s_fm;
      while (fm){
        int g = __ffs(fm)-1; fm &= fm-1;
        int strip = tid / GSZ;                 // 8 strips
        int ol = tid - strip*GSZ;              // 0..47
        float ph = 0.0f;
        const float* wb = w1 + ((size_t)e*HFn + g*GSZ + ol)*Cn;
        for (int i=strip;i<cnt;i+=8) ph += wb[s_act[i]];
        s_h[tid] = ph;
        __syncthreads();
        if (tid < 192) s_h[tid] += s_h[tid+192];
        __syncthreads();
        if (tid < 96)  s_h[tid] += s_h[tid+96];
        __syncthreads();
        bool fire = false;
        if (tid < GSZ){
          float h = s_h[tid] + s_h[tid+GSZ];   // conv-only sum over active channels
          int o = g*GSZ + tid;
          float iv = g1[e*HFn+o] / sqrtf(v1[e*HFn+o] + 1e-5f);
          float q  = iv*b1[e*HFn+o] + (be1[e*HFn+o] - m1[e*HFn+o]*iv) - tau;
          fire = fmaf(iv, h, q) >= 0.0f;       // == BN(conv+b1) >= tau
        }
        if (wid < 2){
          unsigned mm = __ballot_sync(0xffffffffu, fire);
          if (lane==0){ if (wid==0) s_m0 = mm; else s_m1 = mm; }
        }
        __syncthreads();
        if (tid==0){
          int c2 = s_cnt2; unsigned mm = s_m0;
          while (mm){ int b = __ffs(mm)-1; mm &= mm-1; s_fired[c2++] = (short)(g*GSZ + b); }
          mm = s_m1;
          while (mm){ int b = __ffs(mm)-1; mm &= mm-1; s_fired[c2++] = (short)(g*GSZ + 32 + b); }
          s_cnt2 = c2;
        }
        __syncthreads();
      }

      // ---- layer 2: gather fired hidden units (usually zero of them) ----
      int c2 = s_cnt2;
      float a = 0.0f;
      const float* w2b = w2 + ((size_t)e*Cn + tid)*HFn;
      for (int i=0;i<c2;i++) a += w2b[s_fired[i]];
      res[j] += gw * fmaf(inv2, a, add2);
      __syncthreads();   // shared reused next pixel/expert
    }
  }

  float* ob = out + ((size_t)n*Cn + tid)*HWn + p0;
  #pragma unroll
  for (int j=0;j<Pt;j++) ob[j] = res[j];
}

// ---------------- launch ----------------
extern "C" void kernel_launch(void* const* d_in, const int* in_sizes, int n_in,
                              void* d_out, int out_size){
  const float* x      = (const float*)d_in[0];
  const float* rw     = (const float*)d_in[1];
  const float* rb     = (const float*)d_in[2];
  const float* rgam   = (const float*)d_in[3];
  const float* rbeta  = (const float*)d_in[4];
  const float* rmean  = (const float*)d_in[5];
  const float* rvar   = (const float*)d_in[6];
  const float* w1     = (const float*)d_in[7];
  const float* b1     = (const float*)d_in[8];
  const float* g1     = (const float*)d_in[9];
  const float* be1    = (const float*)d_in[10];
  const float* m1     = (const float*)d_in[11];
  const float* v1     = (const float*)d_in[12];
  const float* w2     = (const float*)d_in[13];
  const float* b2     = (const float*)d_in[14];
  const float* g2     = (const float*)d_in[15];
  const float* be2    = (const float*)d_in[16];
  const float* m2     = (const float*)d_in[17];
  const float* v2     = (const float*)d_in[18];
  const float* taus   = (const float*)d_in[19];
  float* out = (float*)d_out;
  (void)in_sizes; (void)n_in;

  k_colmax32<<<dim3(NG, En), Cn>>>(w1);
  k_prep_groups<<<dim3(NG, En), GSZ>>>(g1, be1, m1, v1, b1, taus);
  k_lif<<<Bn*Cn, HWn>>>(x);
  k_logits<<<Nn, 256>>>(rw, rb, rgam, rbeta, rmean, rvar);
  float* auxp = (out_size > OUT_MAIN) ? (out + OUT_MAIN) : nullptr;
  k_gate<<<1, Nn>>>(auxp);
  k_expert<<<dim3(HWn/Pt, Nn), Cn>>>(x, taus, w1, b1, g1, be1, m1, v1,
                                     w2, b2, g2, be2, m2, v2, out);
}

// round 3
// speedup vs baseline: 1.3597x; 1.2325x over previous
#include <cuda_runtime.h>
#include <math.h>

#define Tn   4
#define Bn   32
#define Cn   384
#define HFn  1536
#define HWn  196
#define En   8
#define Nn   128
#define OUT_MAIN (Nn*Cn*HWn)
#define NG   32          // o-groups per expert
#define GSZ  48          // outputs per group (32*48 = 1536)
#define Pt   7           // pixels per expert block (7*28 = 196)

// ---------------- device scratch ----------------
__device__ float g_colmax32[En*Cn*NG];  // [e][c][g] = max_{o in g} w1[e][o][c]
__device__ float g_colmaxA[En*Cn];      // [e][c]    = max over all o
__device__ float g_thrmin32[En*NG];     // per-group conv-domain threshold min (-1e30 = unusable)
__device__ float g_thrall[En];          // min over groups
__device__ int   g_canskip[En];         // all groups usable
__device__ float g_m2c[En*Cn];          // BN2 scale
__device__ float g_a2c[En*Cn];          // BN2( b2 ) fold
__device__ float g_sbar[Nn*Cn];
__device__ float g_logits[Nn*En];
__device__ int   g_sel[Nn*2];
__device__ float g_gate[Nn*2];

// ---------------- prep ----------------
__global__ void k_colmax32(const float* __restrict__ w1){
  int g = blockIdx.x, e = blockIdx.y, c = threadIdx.x;   // 384 threads
  const float* base = w1 + ((size_t)e*HFn + g*GSZ)*Cn + c;
  float m = -1e30f;
  #pragma unroll 8
  for (int o=0;o<GSZ;o++) m = fmaxf(m, base[(size_t)o*Cn]);
  g_colmax32[((size_t)e*Cn + c)*NG + g] = m;
}

__global__ void k_colmaxA(){
  int e = blockIdx.x, c = threadIdx.x;
  const float* p = g_colmax32 + ((size_t)e*Cn + c)*NG;
  float m = -1e30f;
  #pragma unroll
  for (int g=0;g<NG;g++) m = fmaxf(m, p[g]);
  g_colmaxA[e*Cn + c] = m;
}

__global__ void k_prep_groups(const float* __restrict__ g1,const float* __restrict__ be1,
                              const float* __restrict__ m1,const float* __restrict__ v1,
                              const float* __restrict__ b1,const float* __restrict__ taus){
  int g = blockIdx.x, e = blockIdx.y, j = threadIdx.x;   // 48 threads
  int o = g*GSZ + j;
  float tau = taus[e];
  float iv = g1[e*HFn+o] / sqrtf(v1[e*HFn+o] + 1e-5f);
  float sh = be1[e*HFn+o] - m1[e*HFn+o]*iv;
  bool ok = iv > 0.0f;
  float t = ok ? ((tau - sh)/iv - b1[e*HFn+o]) : 1e30f;   // conv-domain threshold
  __shared__ float sm[64];
  if (j < 16) sm[GSZ + j] = 1e30f;
  sm[j] = t;
  int okc = __syncthreads_count(ok);
  for (int s=32;s>=1;s>>=1){
    if (j < s) sm[j] = fminf(sm[j], sm[j+s]);
    __syncthreads();
  }
  if (j==0) g_thrmin32[e*NG + g] = (okc == GSZ) ? sm[0] : -1e30f;
}

__global__ void k_thrall(){
  int e = blockIdx.x, lane = threadIdx.x;   // 32 threads
  float t = g_thrmin32[e*NG + lane];
  bool ok = t > -1e29f;
  float m = t;
  #pragma unroll
  for (int d=16;d>=1;d>>=1) m = fminf(m, __shfl_xor_sync(0xffffffffu, m, d));
  unsigned bm = __ballot_sync(0xffffffffu, ok);
  if (lane==0){ g_thrall[e] = m; g_canskip[e] = (bm == 0xffffffffu); }
}

__global__ void k_prep_l2(const float* __restrict__ g2,const float* __restrict__ be2,
                          const float* __restrict__ m2,const float* __restrict__ v2,
                          const float* __restrict__ b2){
  int e = blockIdx.x, c = threadIdx.x;
  float inv = g2[e*Cn+c] / sqrtf(v2[e*Cn+c] + 1e-5f);
  float sh  = be2[e*Cn+c] - m2[e*Cn+c]*inv;
  g_m2c[e*Cn+c] = inv;
  g_a2c[e*Cn+c] = inv*b2[e*Cn+c] + sh;
}

// ---------------- router ----------------
__global__ void k_lif(const float* __restrict__ x){
  int bc = blockIdx.x;                   // b*Cn + c
  int b = bc / Cn, c = bc % Cn;
  int p = threadIdx.x;                   // 0..195
  float v = 0.0f; int cnt[Tn];
  #pragma unroll
  for (int t=0;t<Tn;t++){
    float xv = x[((size_t)((t*Bn+b)*Cn + c))*HWn + p];
    v += (xv - v)*0.5f;
    bool s = (v - 1.0f) >= 0.0f;
    cnt[t] = __syncthreads_count(s);
    if (s) v = 0.0f;
  }
  if (p==0){
    #pragma unroll
    for (int t=0;t<Tn;t++)
      g_sbar[(t*Bn+b)*Cn + c] = (float)cnt[t] / (float)HWn;
  }
}

__global__ void __launch_bounds__(Cn) k_logits(
    const float* __restrict__ rw, const float* __restrict__ rb,
    const float* __restrict__ rg, const float* __restrict__ rbeta,
    const float* __restrict__ rmean, const float* __restrict__ rvar){
  int n = blockIdx.x, tid = threadIdx.x;  // 384 threads = channel
  int lane = tid & 31, wid = tid >> 5;
  __shared__ float s_red[En][12];
  float s = g_sbar[n*Cn + tid];
  float acc[En];
  #pragma unroll
  for (int e=0;e<En;e++) acc[e] = s * rw[e*Cn + tid];
  #pragma unroll
  for (int e=0;e<En;e++){
    float v = acc[e];
    #pragma unroll
    for (int d=16;d>=1;d>>=1) v += __shfl_xor_sync(0xffffffffu, v, d);
    if (lane==0) s_red[e][wid] = v;
  }
  __syncthreads();
  if (tid < En){
    int e = tid;
    float dot = 0.0f;
    #pragma unroll
    for (int w=0;w<12;w++) dot += s_red[e][w];
    float inv = rg[e] / sqrtf(rvar[e] + 1e-5f);
    g_logits[n*En+e] = inv*(dot + rb[e]) + (rbeta[e] - rmean[e]*inv);
  }
}

__global__ void k_gate(float* __restrict__ auxout){
  int n = threadIdx.x;
  float lg[En];
  #pragma unroll
  for (int e=0;e<En;e++) lg[e] = g_logits[n*En+e];
  float mx = lg[0];
  #pragma unroll
  for (int e=1;e<En;e++) mx = fmaxf(mx, lg[e]);
  float pe[En]; float sum = 0.0f;
  #pragma unroll
  for (int e=0;e<En;e++){ pe[e] = expf(lg[e]-mx); sum += pe[e]; }
  #pragma unroll
  for (int e=0;e<En;e++) pe[e] /= sum;
  int i1 = 0; float p1 = pe[0];
  #pragma unroll
  for (int e=1;e<En;e++) if (pe[e] > p1){ p1 = pe[e]; i1 = e; }
  int i2 = -1; float p2 = -1.0f;
  #pragma unroll
  for (int e=0;e<En;e++) if (e != i1 && pe[e] > p2){ p2 = pe[e]; i2 = e; }
  float ws = p1 + p2;
  g_sel[n*2]   = i1;  g_sel[n*2+1]  = i2;
  g_gate[n*2]  = p1/ws; g_gate[n*2+1] = p2/ws;

  __shared__ float sp[Nn];
  float fp = 0.0f;
  for (int e=0;e<En;e++){
    int cnt = __syncthreads_count(i1==e || i2==e);
    sp[n] = pe[e];
    __syncthreads();
    for (int s=64;s>=1;s>>=1){ if (n<s) sp[n]+=sp[n+s]; __syncthreads(); }
    if (n==0) fp += ((float)cnt/(float)Nn) * (sp[0]/(float)Nn);
    __syncthreads();
  }
  if (n==0 && auxout) auxout[0] = 0.01f * (float)En * fp;
}

// ---------------- main expert kernel: block = (7 pixels, token) ----------------
__global__ void __launch_bounds__(Cn) k_expert(
    const float* __restrict__ x, const float* __restrict__ taus,
    const float* __restrict__ w1, const float* __restrict__ b1,
    const float* __restrict__ g1, const float* __restrict__ be1,
    const float* __restrict__ m1, const float* __restrict__ v1,
    const float* __restrict__ w2,
    float* __restrict__ out){
  int p0 = blockIdx.x * Pt;
  int n  = blockIdx.y;
  int tid = threadIdx.x;     // channel c
  int lane = tid & 31, wid = tid >> 5;

  __shared__ int    s_act[Cn];
  __shared__ float  s_part[256];
  __shared__ float  s_h[Cn];
  __shared__ short  s_fired[HFn];
  __shared__ float  s_ws[12];
  __shared__ int    s_wc[12], s_wo[12];
  __shared__ float  s_ub;
  __shared__ int    s_cnt2;
  __shared__ unsigned s_fm, s_m0, s_m1;

  float xv[Pt], res[Pt];
  const float* xb = x + ((size_t)n*Cn + tid)*HWn + p0;
  #pragma unroll
  for (int j=0;j<Pt;j++) xv[j] = xb[j];

  int   e0  = g_sel[n*2],   e1  = g_sel[n*2+1];
  float gw0 = g_gate[n*2],  gw1 = g_gate[n*2+1];
  #pragma unroll
  for (int j=0;j<Pt;j++) res[j] = xv[j] * (gw0 + gw1);  // residual per selected expert

  for (int k=0;k<2;k++){
    int   e  = k ? e1  : e0;
    float gw = k ? gw1 : gw0;
    float tau  = taus[e];
    float cm   = g_colmaxA[e*Cn + tid];     // register-held per-channel colmax
    float thr  = g_thrall[e];
    int   cskip= g_canskip[e];
    float inv2 = g_m2c[e*Cn + tid];
    float add2 = g_a2c[e*Cn + tid];

    for (int j=0;j<Pt;j++){
      bool cond = (xv[j]/tau - 1.0f) >= 0.0f;   // layer-1 spike, exact reference form
      int cnt = __syncthreads_count(cond);

      // ---- fast path 1: no active channels -> h = 0 -> ub = 0 ----
      if (cnt == 0 && cskip && thr > 1e-3f){
        res[j] += gw * add2;
        continue;                                // uniform across block
      }

      // ---- fast path 2: scalar bound, register-only ----
      unsigned m = __ballot_sync(0xffffffffu, cond);
      float val = cond ? cm : 0.0f;
      #pragma unroll
      for (int d=16;d>=1;d>>=1) val += __shfl_xor_sync(0xffffffffu, val, d);
      if (lane==0){ s_ws[wid] = val; s_wc[wid] = __popc(m); }
      __syncthreads();
      if (tid==0){
        float u = 0.0f;
        #pragma unroll
        for (int w=0;w<12;w++) u += s_ws[w];
        s_ub = u;
      }
      __syncthreads();
      if (cskip && s_ub < thr - 1e-3f){
        res[j] += gw * add2;
        continue;
      }

      // ---- heavy path: compaction + per-group bounds + exact groups ----
      if (tid==0){
        int s=0;
        #pragma unroll
        for (int w=0;w<12;w++){ s_wo[w]=s; s+=s_wc[w]; }
        s_cnt2 = 0;
      }
      __syncthreads();
      if (cond) s_act[s_wo[wid] + __popc(m & ((1u<<lane)-1u))] = tid;
      __syncthreads();

      // coarse per-group upper bound
      if (tid < 256){
        int g = tid & 31, idx = tid >> 5;
        float pp = 0.0f;
        const float* cmp = g_colmax32 + (size_t)e*Cn*NG + g;
        for (int i=idx;i<cnt;i+=8) pp += cmp[(size_t)s_act[i]*NG];
        s_part[tid] = pp;
      }
      __syncthreads();
      if (tid < 128) s_part[tid] += s_part[tid+128];
      __syncthreads();
      if (tid < 64)  s_part[tid] += s_part[tid+64];
      __syncthreads();
      if (wid == 0){
        float ub = s_part[lane] + s_part[lane+32];
        bool fail = ub >= g_thrmin32[e*NG+lane] - 1e-3f;
        unsigned fm = __ballot_sync(0xffffffffu, fail);
        if (lane==0) s_fm = fm;
      }
      __syncthreads();

      unsigned fm = s_fm;
      while (fm){
        int g = __ffs(fm)-1; fm &= fm-1;
        int strip = tid / GSZ;
        int ol = tid - strip*GSZ;
        float ph = 0.0f;
        const float* wb = w1 + ((size_t)e*HFn + g*GSZ + ol)*Cn;
        for (int i=strip;i<cnt;i+=8) ph += wb[s_act[i]];
        s_h[tid] = ph;
        __syncthreads();
        if (tid < 192) s_h[tid] += s_h[tid+192];
        __syncthreads();
        if (tid < 96)  s_h[tid] += s_h[tid+96];
        __syncthreads();
        bool fire = false;
        if (tid < GSZ){
          float h = s_h[tid] + s_h[tid+GSZ];
          int o = g*GSZ + tid;
          float iv = g1[e*HFn+o] / sqrtf(v1[e*HFn+o] + 1e-5f);
          float q  = iv*b1[e*HFn+o] + (be1[e*HFn+o] - m1[e*HFn+o]*iv) - tau;
          fire = fmaf(iv, h, q) >= 0.0f;
        }
        if (wid < 2){
          unsigned mm = __ballot_sync(0xffffffffu, fire);
          if (lane==0){ if (wid==0) s_m0 = mm; else s_m1 = mm; }
        }
        __syncthreads();
        if (tid==0){
          int c2 = s_cnt2; unsigned mm = s_m0;
          while (mm){ int b = __ffs(mm)-1; mm &= mm-1; s_fired[c2++] = (short)(g*GSZ + b); }
          mm = s_m1;
          while (mm){ int b = __ffs(mm)-1; mm &= mm-1; s_fired[c2++] = (short)(g*GSZ + 32 + b); }
          s_cnt2 = c2;
        }
        __syncthreads();
      }

      int c2 = s_cnt2;
      float a = 0.0f;
      const float* w2b = w2 + ((size_t)e*Cn + tid)*HFn;
      for (int i=0;i<c2;i++) a += w2b[s_fired[i]];
      res[j] += gw * fmaf(inv2, a, add2);
      __syncthreads();
    }
  }

  float* ob = out + ((size_t)n*Cn + tid)*HWn + p0;
  #pragma unroll
  for (int j=0;j<Pt;j++) ob[j] = res[j];
}

// ---------------- launch ----------------
extern "C" void kernel_launch(void* const* d_in, const int* in_sizes, int n_in,
                              void* d_out, int out_size){
  const float* x      = (const float*)d_in[0];
  const float* rw     = (const float*)d_in[1];
  const float* rb     = (const float*)d_in[2];
  const float* rgam   = (const float*)d_in[3];
  const float* rbeta  = (const float*)d_in[4];
  const float* rmean  = (const float*)d_in[5];
  const float* rvar   = (const float*)d_in[6];
  const float* w1     = (const float*)d_in[7];
  const float* b1     = (const float*)d_in[8];
  const float* g1     = (const float*)d_in[9];
  const float* be1    = (const float*)d_in[10];
  const float* m1     = (const float*)d_in[11];
  const float* v1     = (const float*)d_in[12];
  const float* w2     = (const float*)d_in[13];
  const float* b2     = (const float*)d_in[14];
  const float* g2     = (const float*)d_in[15];
  const float* be2    = (const float*)d_in[16];
  const float* m2     = (const float*)d_in[17];
  const float* v2     = (const float*)d_in[18];
  const float* taus   = (const float*)d_in[19];
  float* out = (float*)d_out;
  (void)in_sizes; (void)n_in;

  k_colmax32<<<dim3(NG, En), Cn>>>(w1);
  k_colmaxA<<<En, Cn>>>();
  k_prep_groups<<<dim3(NG, En), GSZ>>>(g1, be1, m1, v1, b1, taus);
  k_thrall<<<En, 32>>>();
  k_prep_l2<<<En, Cn>>>(g2, be2, m2, v2, b2);
  k_lif<<<Bn*Cn, HWn>>>(x);
  k_logits<<<Nn, Cn>>>(rw, rb, rgam, rbeta, rmean, rvar);
  float* auxp = (out_size > OUT_MAIN) ? (out + OUT_MAIN) : nullptr;
  k_gate<<<1, Nn>>>(auxp);
  k_expert<<<dim3(HWn/Pt, Nn), Cn>>>(x, taus, w1, b1, g1, be1, m1, v1, w2, out);
}

// round 4
// speedup vs baseline: 1.4706x; 1.0816x over previous
#include <cuda_runtime.h>
#include <math.h>

#define Tn   4
#define Bn   32
#define Cn   384
#define HFn  1536
#define HWn  196
#define En   8
#define Nn   128
#define OUT_MAIN (Nn*Cn*HWn)
#define NG   32          // o-groups per expert
#define GSZ  48          // outputs per group
#define Pt   7           // pixels per expert block

// ---------------- device scratch ----------------
__device__ float g_colmax32[En*Cn*NG];  // [e][c][g] = max_{o in g} w1[e][o][c]
__device__ float g_colmaxA[En*Cn];      // [e][c] max over all o
__device__ float g_thrmin32[En*NG];     // per-group conv-domain threshold min (-1e30 = unusable)
__device__ float g_thrall[En];          // min over groups (-1e30 if any unusable)
__device__ float g_maxcm[En];           // max over c of colmaxA
__device__ float g_m2c[En*Cn];          // BN2 scale
__device__ float g_a2c[En*Cn];          // BN2 bias fold (b2 included)
__device__ float g_sbar[Nn*Cn];
__device__ int   g_sel[Nn*2];
__device__ float g_gate[Nn*2];
__device__ float g_probs[Nn*En];

// ---------------- prep 1: colmax table ----------------
__global__ void k_colmax32(const float* __restrict__ w1){
  int g = blockIdx.x, e = blockIdx.y, c = threadIdx.x;   // 384 threads
  const float* base = w1 + ((size_t)e*HFn + g*GSZ)*Cn + c;
  float m = -1e30f;
  #pragma unroll 8
  for (int o=0;o<GSZ;o++) m = fmaxf(m, base[(size_t)o*Cn]);
  g_colmax32[((size_t)e*Cn + c)*NG + g] = m;
}

// ---------------- prep 2: everything else, one block per expert ----------------
__global__ void __launch_bounds__(Cn) k_prep2(
    const float* __restrict__ g1, const float* __restrict__ be1,
    const float* __restrict__ m1, const float* __restrict__ v1,
    const float* __restrict__ b1,
    const float* __restrict__ g2, const float* __restrict__ be2,
    const float* __restrict__ m2, const float* __restrict__ v2,
    const float* __restrict__ b2,
    const float* __restrict__ taus){
  int e = blockIdx.x, tid = threadIdx.x;
  int lane = tid & 31, wid = tid >> 5;
  __shared__ float s_thr[HFn];
  __shared__ float s_red[12];
  float tau = taus[e];

  #pragma unroll
  for (int r=0;r<4;r++){
    int o = tid + r*Cn;
    float iv = g1[e*HFn+o] * rsqrtf(v1[e*HFn+o] + 1e-5f);
    float sh = be1[e*HFn+o] - m1[e*HFn+o]*iv;
    s_thr[o] = (iv > 0.0f) ? ((tau - sh)/iv - b1[e*HFn+o]) : -1e30f;  // conv-domain thr
  }

  // colmaxA + block max (maxcm)
  const float* p = g_colmax32 + ((size_t)e*Cn + tid)*NG;
  float mx = -1e30f;
  #pragma unroll
  for (int g=0;g<NG;g++) mx = fmaxf(mx, p[g]);
  g_colmaxA[e*Cn + tid] = mx;
  float wmx = mx;
  #pragma unroll
  for (int d=16;d>=1;d>>=1) wmx = fmaxf(wmx, __shfl_xor_sync(0xffffffffu, wmx, d));
  if (lane==0) s_red[wid] = wmx;

  // BN2 fold
  {
    float inv = g2[e*Cn+tid] * rsqrtf(v2[e*Cn+tid] + 1e-5f);
    float sh  = be2[e*Cn+tid] - m2[e*Cn+tid]*inv;
    g_m2c[e*Cn+tid] = inv;
    g_a2c[e*Cn+tid] = inv*b2[e*Cn+tid] + sh;
  }
  __syncthreads();

  if (tid < NG){
    int g = tid;
    float mn = 1e30f;
    #pragma unroll 8
    for (int i=0;i<GSZ;i++) mn = fminf(mn, s_thr[g*GSZ + i]);
    g_thrmin32[e*NG + g] = mn;
    float ta = mn;
    #pragma unroll
    for (int d=16;d>=1;d>>=1) ta = fminf(ta, __shfl_xor_sync(0xffffffffu, ta, d));
    if (tid==0) g_thrall[e] = ta;        // -1e30 if any group unusable -> tests fail
  }
  if (tid==32){
    float mm = -1e30f;
    #pragma unroll
    for (int w=0;w<12;w++) mm = fmaxf(mm, s_red[w]);
    g_maxcm[e] = mm;
  }
}

// ---------------- router ----------------
__global__ void k_lif(const float* __restrict__ x){
  int bc = blockIdx.x;                   // b*Cn + c
  int b = bc / Cn, c = bc % Cn;
  int p = threadIdx.x;                   // 0..195
  float v = 0.0f; int cnt[Tn];
  #pragma unroll
  for (int t=0;t<Tn;t++){
    float xv = x[((size_t)((t*Bn+b)*Cn + c))*HWn + p];
    v += (xv - v)*0.5f;
    bool s = (v - 1.0f) >= 0.0f;
    cnt[t] = __syncthreads_count(s);
    if (s) v = 0.0f;
  }
  if (p==0){
    #pragma unroll
    for (int t=0;t<Tn;t++)
      g_sbar[(t*Bn+b)*Cn + c] = (float)cnt[t] / (float)HWn;
  }
}

// logits + softmax + top2 + gate, one block per token
__global__ void __launch_bounds__(Cn) k_logits_gate(
    const float* __restrict__ rw, const float* __restrict__ rb,
    const float* __restrict__ rg, const float* __restrict__ rbeta,
    const float* __restrict__ rmean, const float* __restrict__ rvar){
  int n = blockIdx.x, tid = threadIdx.x;
  int lane = tid & 31, wid = tid >> 5;
  __shared__ float s_red[En][13];
  __shared__ float s_lg[En];
  float s = g_sbar[n*Cn + tid];
  #pragma unroll
  for (int e=0;e<En;e++){
    float v = s * rw[e*Cn + tid];
    #pragma unroll
    for (int d=16;d>=1;d>>=1) v += __shfl_xor_sync(0xffffffffu, v, d);
    if (lane==0) s_red[e][wid] = v;
  }
  __syncthreads();
  if (tid < En){
    int e = tid;
    float dot = 0.0f;
    #pragma unroll
    for (int w=0;w<12;w++) dot += s_red[e][w];
    float inv = rg[e] * rsqrtf(rvar[e] + 1e-5f);
    s_lg[e] = inv*(dot + rb[e]) + (rbeta[e] - rmean[e]*inv);
  }
  __syncthreads();
  if (tid == 0){
    float lg[En], pe[En];
    float mx = -1e30f;
    #pragma unroll
    for (int e=0;e<En;e++){ lg[e] = s_lg[e]; mx = fmaxf(mx, lg[e]); }
    float sum = 0.0f;
    #pragma unroll
    for (int e=0;e<En;e++){ pe[e] = expf(lg[e]-mx); sum += pe[e]; }
    #pragma unroll
    for (int e=0;e<En;e++){ pe[e] /= sum; g_probs[n*En+e] = pe[e]; }
    int i1 = 0; float p1 = pe[0];
    #pragma unroll
    for (int e=1;e<En;e++) if (pe[e] > p1){ p1 = pe[e]; i1 = e; }
    int i2 = -1; float p2 = -1.0f;
    #pragma unroll
    for (int e=0;e<En;e++) if (e != i1 && pe[e] > p2){ p2 = pe[e]; i2 = e; }
    float ws = p1 + p2;
    g_sel[n*2]   = i1;    g_sel[n*2+1]  = i2;
    g_gate[n*2]  = p1/ws; g_gate[n*2+1] = p2/ws;
  }
}

__global__ void k_aux(float* __restrict__ auxout){
  int n = threadIdx.x;   // 128
  int i1 = g_sel[n*2], i2 = g_sel[n*2+1];
  float pe[En];
  #pragma unroll
  for (int e=0;e<En;e++) pe[e] = g_probs[n*En+e];
  __shared__ float sp[Nn];
  float fp = 0.0f;
  for (int e=0;e<En;e++){
    int cnt = __syncthreads_count(i1==e || i2==e);
    sp[n] = pe[e];
    __syncthreads();
    for (int s=64;s>=1;s>>=1){ if (n<s) sp[n]+=sp[n+s]; __syncthreads(); }
    if (n==0) fp += ((float)cnt/(float)Nn) * (sp[0]/(float)Nn);
    __syncthreads();
  }
  if (n==0 && auxout) auxout[0] = 0.01f * (float)En * fp;
}

// ---------------- main expert kernel ----------------
__global__ void __launch_bounds__(Cn) k_expert(
    const float* __restrict__ x, const float* __restrict__ taus,
    const float* __restrict__ w1, const float* __restrict__ b1,
    const float* __restrict__ g1, const float* __restrict__ be1,
    const float* __restrict__ m1, const float* __restrict__ v1,
    const float* __restrict__ w2,
    float* __restrict__ out){
  int p0 = blockIdx.x * Pt;
  int n  = blockIdx.y;
  int tid = threadIdx.x;     // channel c
  int lane = tid & 31, wid = tid >> 5;

  __shared__ unsigned s_mask[12];
  __shared__ float  s_part[32*13];
  __shared__ float  s_ws[12];
  __shared__ int    s_act[Cn];
  __shared__ float  s_h[Cn];
  __shared__ short  s_fired[HFn];
  __shared__ float  s_ub;
  __shared__ int    s_cnt2;
  __shared__ unsigned s_fm, s_m0, s_m1;

  float xv[Pt], res[Pt];
  const float* xb = x + ((size_t)n*Cn + tid)*HWn + p0;
  #pragma unroll
  for (int j=0;j<Pt;j++) xv[j] = xb[j];

  int   e0  = g_sel[n*2],   e1  = g_sel[n*2+1];
  float gw0 = g_gate[n*2],  gw1 = g_gate[n*2+1];
  #pragma unroll
  for (int j=0;j<Pt;j++) res[j] = xv[j] * (gw0 + gw1);

  for (int k=0;k<2;k++){
    int   e  = k ? e1  : e0;
    float gw = k ? gw1 : gw0;
    float tau   = taus[e];
    float cmA   = g_colmaxA[e*Cn + tid];
    float thr   = g_thrall[e];           // -1e30 if unusable -> all tests fail
    float maxcm = g_maxcm[e];
    float inv2  = g_m2c[e*Cn + tid];
    float add2  = g_a2c[e*Cn + tid];
    float thrm  = thr - 1e-3f;

    for (int j=0;j<Pt;j++){
      bool cond = (xv[j]/tau - 1.0f) >= 0.0f;   // layer-1 spike, exact reference form
      int cnt = __syncthreads_count(cond);

      // ---- tier 0: cnt-only bound (no extra barriers/loads) ----
      if ((float)cnt * maxcm < thrm){
        res[j] += gw * add2;
        continue;
      }

      // ---- tier 1: per-channel scalar bound ----
      unsigned m = __ballot_sync(0xffffffffu, cond);
      float val = cond ? cmA : 0.0f;
      #pragma unroll
      for (int d=16;d>=1;d>>=1) val += __shfl_xor_sync(0xffffffffu, val, d);
      if (lane==0) s_ws[wid] = val;
      __syncthreads();
      if (tid==0){
        float u = 0.0f;
        #pragma unroll
        for (int w=0;w<12;w++) u += s_ws[w];
        s_ub = u;
      }
      __syncthreads();
      if (s_ub < thrm){
        res[j] += gw * add2;
        continue;
      }

      // ---- tier 2: per-group bound, warp-local gather (no compaction) ----
      {
        float pp = 0.0f;
        unsigned mm = m;
        const float* cmp = g_colmax32 + (size_t)e*Cn*NG + lane;
        int cb = wid*32;
        while (mm){
          int b = __ffs(mm)-1; mm &= mm-1;
          pp += cmp[(size_t)(cb + b)*NG];
        }
        s_part[lane*13 + wid] = pp;
        if (lane==0) s_mask[wid] = m;
      }
      __syncthreads();
      if (tid < NG){
        float ub = 0.0f;
        #pragma unroll
        for (int s=0;s<12;s++) ub += s_part[tid*13 + s];
        bool fail = ub >= g_thrmin32[e*NG + tid] - 1e-3f;
        unsigned fm = __ballot_sync(0xffffffffu, fail);
        if (tid==0) s_fm = fm;
      }
      __syncthreads();
      unsigned fm = s_fm;
      if (fm == 0){
        res[j] += gw * add2;
        continue;
      }

      // ---- tier 3: exact compute for failing groups (rare) ----
      if (tid==0){
        int s = 0;
        #pragma unroll
        for (int w=0;w<12;w++){
          unsigned mm = s_mask[w];
          while (mm){ int b = __ffs(mm)-1; mm &= mm-1; s_act[s++] = w*32 + b; }
        }
        s_cnt2 = 0;
      }
      __syncthreads();

      while (fm){
        int g = __ffs(fm)-1; fm &= fm-1;
        int strip = tid / GSZ;                 // 8 strips
        int ol = tid - strip*GSZ;              // 0..47
        float ph = 0.0f;
        const float* wb = w1 + ((size_t)e*HFn + g*GSZ + ol)*Cn;
        for (int i=strip;i<cnt;i+=8) ph += wb[s_act[i]];
        s_h[tid] = ph;
        __syncthreads();
        if (tid < 192) s_h[tid] += s_h[tid+192];
        __syncthreads();
        if (tid < 96)  s_h[tid] += s_h[tid+96];
        __syncthreads();
        bool fire = false;
        if (tid < GSZ){
          float h = s_h[tid] + s_h[tid+GSZ];
          int o = g*GSZ + tid;
          float iv = g1[e*HFn+o] * rsqrtf(v1[e*HFn+o] + 1e-5f);
          float q  = iv*b1[e*HFn+o] + (be1[e*HFn+o] - m1[e*HFn+o]*iv) - tau;
          fire = fmaf(iv, h, q) >= 0.0f;
        }
        if (wid < 2){
          unsigned mm2 = __ballot_sync(0xffffffffu, fire);
          if (lane==0){ if (wid==0) s_m0 = mm2; else s_m1 = mm2; }
        }
        __syncthreads();
        if (tid==0){
          int c2 = s_cnt2; unsigned mm2 = s_m0;
          while (mm2){ int b = __ffs(mm2)-1; mm2 &= mm2-1; s_fired[c2++] = (short)(g*GSZ + b); }
          mm2 = s_m1;
          while (mm2){ int b = __ffs(mm2)-1; mm2 &= mm2-1; s_fired[c2++] = (short)(g*GSZ + 32 + b); }
          s_cnt2 = c2;
        }
        __syncthreads();
      }

      int c2 = s_cnt2;
      float a = 0.0f;
      const float* w2b = w2 + ((size_t)e*Cn + tid)*HFn;
      for (int i=0;i<c2;i++) a += w2b[s_fired[i]];
      res[j] += gw * fmaf(inv2, a, add2);
      __syncthreads();
    }
  }

  float* ob = out + ((size_t)n*Cn + tid)*HWn + p0;
  #pragma unroll
  for (int j=0;j<Pt;j++) ob[j] = res[j];
}

// ---------------- launch ----------------
extern "C" void kernel_launch(void* const* d_in, const int* in_sizes, int n_in,
                              void* d_out, int out_size){
  const float* x      = (const float*)d_in[0];
  const float* rw     = (const float*)d_in[1];
  const float* rb     = (const float*)d_in[2];
  const float* rgam   = (const float*)d_in[3];
  const float* rbeta  = (const float*)d_in[4];
  const float* rmean  = (const float*)d_in[5];
  const float* rvar   = (const float*)d_in[6];
  const float* w1     = (const float*)d_in[7];
  const float* b1     = (const float*)d_in[8];
  const float* g1     = (const float*)d_in[9];
  const float* be1    = (const float*)d_in[10];
  const float* m1     = (const float*)d_in[11];
  const float* v1     = (const float*)d_in[12];
  const float* w2     = (const float*)d_in[13];
  const float* b2     = (const float*)d_in[14];
  const float* g2     = (const float*)d_in[15];
  const float* be2    = (const float*)d_in[16];
  const float* m2     = (const float*)d_in[17];
  const float* v2     = (const float*)d_in[18];
  const float* taus   = (const float*)d_in[19];
  float* out = (float*)d_out;
  (void)in_sizes; (void)n_in;

  k_colmax32<<<dim3(NG, En), Cn>>>(w1);
  k_prep2<<<En, Cn>>>(g1, be1, m1, v1, b1, g2, be2, m2, v2, b2, taus);
  k_lif<<<Bn*Cn, HWn>>>(x);
  k_logits_gate<<<Nn, Cn>>>(rw, rb, rgam, rbeta, rmean, rvar);
  float* auxp = (out_size > OUT_MAIN) ? (out + OUT_MAIN) : nullptr;
  k_aux<<<1, Nn>>>(auxp);
  k_expert<<<dim3(HWn/Pt, Nn), Cn>>>(x, taus, w1, b1, g1, be1, m1, v1, w2, out);
}

// round 5
// speedup vs baseline: 2.0603x; 1.4010x over previous
#include <cuda_runtime.h>
#include <math.h>

#define Tn   4
#define Bn   32
#define Cn   384
#define HFn  1536
#define HWn  196
#define En   8
#define Nn   128
#define OUT_MAIN (Nn*Cn*HWn)
#define NG   32          // o-groups per expert
#define GSZ  48          // outputs per group
#define NR   12          // channel registers per lane (12*32 = 384)
#define FULLMASK 0xffffffffu

// ---------------- device scratch ----------------
__device__ float g_colmax32[En*Cn*NG];  // [e][c][g] = max_{o in g} w1[e][o][c]
__device__ float g_thrmin32[En*NG];     // per-group conv-domain threshold min (-1e30 = unusable)
__device__ float g_thrall[En];          // min over groups (-1e30 if any unusable)
__device__ float g_maxcm[En];           // max over (c) of colmaxA
__device__ float g_m2c[En*Cn];          // BN2 scale
__device__ float g_a2c[En*Cn];          // BN2 bias fold (b2 included)
__device__ float g_sbar[Nn*Cn];
__device__ int   g_sel[Nn*2];
__device__ float g_gate[Nn*2];
__device__ float g_probs[Nn*En];

// ---------------- prep 1: colmax table ----------------
__global__ void k_colmax32(const float* __restrict__ w1){
  int g = blockIdx.x, e = blockIdx.y, c = threadIdx.x;   // 384 threads
  const float* base = w1 + ((size_t)e*HFn + g*GSZ)*Cn + c;
  float m = -1e30f;
  #pragma unroll 8
  for (int o=0;o<GSZ;o++) m = fmaxf(m, base[(size_t)o*Cn]);
  g_colmax32[((size_t)e*Cn + c)*NG + g] = m;
}

// ---------------- prep 2: thresholds, maxes, BN2 fold ----------------
__global__ void __launch_bounds__(Cn) k_prep2(
    const float* __restrict__ g1, const float* __restrict__ be1,
    const float* __restrict__ m1, const float* __restrict__ v1,
    const float* __restrict__ b1,
    const float* __restrict__ g2, const float* __restrict__ be2,
    const float* __restrict__ m2, const float* __restrict__ v2,
    const float* __restrict__ b2,
    const float* __restrict__ taus){
  int e = blockIdx.x, tid = threadIdx.x;
  int lane = tid & 31, wid = tid >> 5;
  __shared__ float s_thr[HFn];
  __shared__ float s_red[12];
  float tau = taus[e];

  #pragma unroll
  for (int r=0;r<4;r++){
    int o = tid + r*Cn;
    float iv = g1[e*HFn+o] * rsqrtf(v1[e*HFn+o] + 1e-5f);
    float sh = be1[e*HFn+o] - m1[e*HFn+o]*iv;
    s_thr[o] = (iv > 0.0f) ? ((tau - sh)/iv - b1[e*HFn+o]) : -1e30f;  // conv-domain thr
  }

  // per-channel max over all o, then block max
  const float* p = g_colmax32 + ((size_t)e*Cn + tid)*NG;
  float mx = -1e30f;
  #pragma unroll
  for (int g=0;g<NG;g++) mx = fmaxf(mx, p[g]);
  float wmx = mx;
  #pragma unroll
  for (int d=16;d>=1;d>>=1) wmx = fmaxf(wmx, __shfl_xor_sync(FULLMASK, wmx, d));
  if (lane==0) s_red[wid] = wmx;

  // BN2 fold
  {
    float inv = g2[e*Cn+tid] * rsqrtf(v2[e*Cn+tid] + 1e-5f);
    float sh  = be2[e*Cn+tid] - m2[e*Cn+tid]*inv;
    g_m2c[e*Cn+tid] = inv;
    g_a2c[e*Cn+tid] = inv*b2[e*Cn+tid] + sh;
  }
  __syncthreads();

  if (tid < NG){
    int g = tid;
    float mn = 1e30f;
    #pragma unroll 8
    for (int i=0;i<GSZ;i++) mn = fminf(mn, s_thr[g*GSZ + i]);
    g_thrmin32[e*NG + g] = mn;
    float ta = mn;
    #pragma unroll
    for (int d=16;d>=1;d>>=1) ta = fminf(ta, __shfl_xor_sync(FULLMASK, ta, d));
    if (tid==0) g_thrall[e] = ta;
  }
  if (tid==32){
    float mm = -1e30f;
    #pragma unroll
    for (int w=0;w<12;w++) mm = fmaxf(mm, s_red[w]);
    g_maxcm[e] = mm;
  }
}

// ---------------- router ----------------
__global__ void k_lif(const float* __restrict__ x){
  int bc = blockIdx.x;                   // b*Cn + c
  int b = bc / Cn, c = bc % Cn;
  int p = threadIdx.x;                   // 0..195
  float v = 0.0f; int cnt[Tn];
  #pragma unroll
  for (int t=0;t<Tn;t++){
    float xv = x[((size_t)((t*Bn+b)*Cn + c))*HWn + p];
    v += (xv - v)*0.5f;
    bool s = (v - 1.0f) >= 0.0f;
    cnt[t] = __syncthreads_count(s);
    if (s) v = 0.0f;
  }
  if (p==0){
    #pragma unroll
    for (int t=0;t<Tn;t++)
      g_sbar[(t*Bn+b)*Cn + c] = (float)cnt[t] / (float)HWn;
  }
}

// logits + softmax + top2 + gate, one block per token
__global__ void __launch_bounds__(Cn) k_logits_gate(
    const float* __restrict__ rw, const float* __restrict__ rb,
    const float* __restrict__ rg, const float* __restrict__ rbeta,
    const float* __restrict__ rmean, const float* __restrict__ rvar){
  int n = blockIdx.x, tid = threadIdx.x;
  int lane = tid & 31, wid = tid >> 5;
  __shared__ float s_red[En][13];
  __shared__ float s_lg[En];
  float s = g_sbar[n*Cn + tid];
  #pragma unroll
  for (int e=0;e<En;e++){
    float v = s * rw[e*Cn + tid];
    #pragma unroll
    for (int d=16;d>=1;d>>=1) v += __shfl_xor_sync(FULLMASK, v, d);
    if (lane==0) s_red[e][wid] = v;
  }
  __syncthreads();
  if (tid < En){
    int e = tid;
    float dot = 0.0f;
    #pragma unroll
    for (int w=0;w<12;w++) dot += s_red[e][w];
    float inv = rg[e] * rsqrtf(rvar[e] + 1e-5f);
    s_lg[e] = inv*(dot + rb[e]) + (rbeta[e] - rmean[e]*inv);
  }
  __syncthreads();
  if (tid == 0){
    float lg[En], pe[En];
    float mx = -1e30f;
    #pragma unroll
    for (int e=0;e<En;e++){ lg[e] = s_lg[e]; mx = fmaxf(mx, lg[e]); }
    float sum = 0.0f;
    #pragma unroll
    for (int e=0;e<En;e++){ pe[e] = expf(lg[e]-mx); sum += pe[e]; }
    #pragma unroll
    for (int e=0;e<En;e++){ pe[e] /= sum; g_probs[n*En+e] = pe[e]; }
    int i1 = 0; float p1 = pe[0];
    #pragma unroll
    for (int e=1;e<En;e++) if (pe[e] > p1){ p1 = pe[e]; i1 = e; }
    int i2 = -1; float p2 = -1.0f;
    #pragma unroll
    for (int e=0;e<En;e++) if (e != i1 && pe[e] > p2){ p2 = pe[e]; i2 = e; }
    float ws = p1 + p2;
    g_sel[n*2]   = i1;    g_sel[n*2+1]  = i2;
    g_gate[n*2]  = p1/ws; g_gate[n*2+1] = p2/ws;
  }
}

__global__ void k_aux(float* __restrict__ auxout){
  int n = threadIdx.x;   // 128
  int i1 = g_sel[n*2], i2 = g_sel[n*2+1];
  float pe[En];
  #pragma unroll
  for (int e=0;e<En;e++) pe[e] = g_probs[n*En+e];
  __shared__ float sp[Nn];
  float fp = 0.0f;
  for (int e=0;e<En;e++){
    int cnt = __syncthreads_count(i1==e || i2==e);
    sp[n] = pe[e];
    __syncthreads();
    for (int s=64;s>=1;s>>=1){ if (n<s) sp[n]+=sp[n+s]; __syncthreads(); }
    if (n==0) fp += ((float)cnt/(float)Nn) * (sp[0]/(float)Nn);
    __syncthreads();
  }
  if (n==0 && auxout) auxout[0] = 0.01f * (float)En * fp;
}

// ---------------- main expert kernel: one WARP per (token, 7-pixel tile) ----------------
// No block barriers anywhere. Lane owns channels c = r*32 + lane, r = 0..11.
__global__ void __launch_bounds__(256) k_expert(
    const float* __restrict__ x, const float* __restrict__ taus,
    const float* __restrict__ w1, const float* __restrict__ b1,
    const float* __restrict__ g1, const float* __restrict__ be1,
    const float* __restrict__ m1, const float* __restrict__ v1,
    const float* __restrict__ w2,
    float* __restrict__ out){
  int wu   = blockIdx.x*8 + (threadIdx.x >> 5);   // 0..3583 (= Nn*28)
  int lane = threadIdx.x & 31;
  int n  = wu / 28;
  int p0 = (wu - n*28) * 7;

  int   e0  = g_sel[n*2],   e1  = g_sel[n*2+1];
  float gw0 = g_gate[n*2],  gw1 = g_gate[n*2+1];
  float tau0 = taus[e0],  tau1 = taus[e1];
  float thr0 = g_thrall[e0] - 1e-3f, thr1 = g_thrall[e1] - 1e-3f;
  float mc0  = g_maxcm[e0],          mc1  = g_maxcm[e1];

  float add2_0[NR], add2_1[NR];
  #pragma unroll
  for (int r=0;r<NR;r++){
    add2_0[r] = g_a2c[e0*Cn + r*32 + lane];
    add2_1[r] = g_a2c[e1*Cn + r*32 + lane];
  }

  for (int j=0;j<7;j++){
    int p = p0 + j;
    float xv[NR], res[NR];
    const float* xb = x + ((size_t)n*Cn + lane)*HWn + p;
    #pragma unroll
    for (int r=0;r<NR;r++) xv[r] = xb[(size_t)r*32*HWn];
    #pragma unroll
    for (int r=0;r<NR;r++) res[r] = xv[r] * (gw0 + gw1);   // residual per selected expert

    #pragma unroll
    for (int k=0;k<2;k++){
      int   e   = k ? e1   : e0;
      float gw  = k ? gw1  : gw0;
      float tau = k ? tau1 : tau0;
      float thr = k ? thr1 : thr0;
      float mc  = k ? mc1  : mc0;

      // ---- layer-1 spike masks (warp-synchronous) ----
      unsigned msk[NR]; int cnt = 0;
      #pragma unroll
      for (int r=0;r<NR;r++){
        msk[r] = __ballot_sync(FULLMASK, (xv[r]/tau - 1.0f) >= 0.0f);
        cnt += __popc(msk[r]);
      }

      // ---- tier 0: cnt-only bound (warp-uniform, no loads) ----
      if ((float)cnt * mc < thr){
        #pragma unroll
        for (int r=0;r<NR;r++) res[r] += gw * (k ? add2_1[r] : add2_0[r]);
        continue;
      }

      // ---- tier 2: per-group bound; lane = group g. Coalesced gathers, MLP over r ----
      float ub = 0.0f;
      {
        const float* cmB = g_colmax32 + (size_t)e*Cn*NG + lane;
        float pr[4] = {0.f,0.f,0.f,0.f};
        #pragma unroll
        for (int r=0;r<NR;r++){
          unsigned mm = msk[r];
          float pp = 0.0f;
          while (mm){
            int b = __ffs(mm)-1; mm &= mm-1;
            pp += cmB[(size_t)(r*32 + b)*NG];
          }
          pr[r & 3] += pp;
        }
        ub = (pr[0]+pr[1]) + (pr[2]+pr[3]);
      }
      bool fail = ub >= g_thrmin32[e*NG + lane] - 1e-3f;
      unsigned fm = __ballot_sync(FULLMASK, fail);
      if (fm == 0){
        #pragma unroll
        for (int r=0;r<NR;r++) res[r] += gw * (k ? add2_1[r] : add2_0[r]);
        continue;
      }

      // ---- tier 3: exact compute for failing groups (rare), warp-local ----
      float a[NR];
      #pragma unroll
      for (int r=0;r<NR;r++) a[r] = 0.0f;
      int nf = 0;
      while (fm){
        int g = __ffs(fm)-1; fm &= fm-1;
        // h for 48 outputs: lane -> o = g*48+lane ; lanes 0..15 also o2 = g*48+32+lane
        float h0 = 0.0f, h1 = 0.0f;
        const float* w1b = w1 + ((size_t)e*HFn + g*GSZ)*Cn;
        const float* w1r0 = w1b + (size_t)lane*Cn;
        const float* w1r1 = w1b + (size_t)(32+lane)*Cn;
        #pragma unroll
        for (int r=0;r<NR;r++){
          unsigned mm = msk[r];
          while (mm){
            int b = __ffs(mm)-1; mm &= mm-1;
            int c = r*32 + b;
            h0 += w1r0[c];
            if (lane < 16) h1 += w1r1[c];
          }
        }
        int o0 = g*GSZ + lane;
        float iv0 = g1[e*HFn+o0] * rsqrtf(v1[e*HFn+o0] + 1e-5f);
        float q0  = iv0*b1[e*HFn+o0] + (be1[e*HFn+o0] - m1[e*HFn+o0]*iv0) - tau;
        bool f0 = fmaf(iv0, h0, q0) >= 0.0f;
        bool f1 = false;
        if (lane < 16){
          int o1 = g*GSZ + 32 + lane;
          float iv1 = g1[e*HFn+o1] * rsqrtf(v1[e*HFn+o1] + 1e-5f);
          float q1  = iv1*b1[e*HFn+o1] + (be1[e*HFn+o1] - m1[e*HFn+o1]*iv1) - tau;
          f1 = fmaf(iv1, h1, q1) >= 0.0f;
        }
        unsigned fma0 = __ballot_sync(FULLMASK, f0);
        unsigned fma1 = __ballot_sync(FULLMASK, f1);   // only low 16 bits can be set
        // layer-2 accumulation for fired outputs (fixed order)
        unsigned t = fma0;
        while (t){
          int b = __ffs(t)-1; t &= t-1;
          int o = g*GSZ + b;
          const float* w2b = w2 + ((size_t)e*Cn + lane)*HFn + o;
          #pragma unroll
          for (int r=0;r<NR;r++) a[r] += w2b[(size_t)r*32*HFn];
          nf++;
        }
        t = fma1;
        while (t){
          int b = __ffs(t)-1; t &= t-1;
          int o = g*GSZ + 32 + b;
          const float* w2b = w2 + ((size_t)e*Cn + lane)*HFn + o;
          #pragma unroll
          for (int r=0;r<NR;r++) a[r] += w2b[(size_t)r*32*HFn];
          nf++;
        }
      }
      if (nf){
        #pragma unroll
        for (int r=0;r<NR;r++){
          float inv2 = g_m2c[e*Cn + r*32 + lane];
          res[r] += gw * fmaf(inv2, a[r], (k ? add2_1[r] : add2_0[r]));
        }
      } else {
        #pragma unroll
        for (int r=0;r<NR;r++) res[r] += gw * (k ? add2_1[r] : add2_0[r]);
      }
    }

    float* ob = out + ((size_t)n*Cn + lane)*HWn + p;
    #pragma unroll
    for (int r=0;r<NR;r++) ob[(size_t)r*32*HWn] = res[r];
  }
}

// ---------------- launch ----------------
extern "C" void kernel_launch(void* const* d_in, const int* in_sizes, int n_in,
                              void* d_out, int out_size){
  const float* x      = (const float*)d_in[0];
  const float* rw     = (const float*)d_in[1];
  const float* rb     = (const float*)d_in[2];
  const float* rgam   = (const float*)d_in[3];
  const float* rbeta  = (const float*)d_in[4];
  const float* rmean  = (const float*)d_in[5];
  const float* rvar   = (const float*)d_in[6];
  const float* w1     = (const float*)d_in[7];
  const float* b1     = (const float*)d_in[8];
  const float* g1     = (const float*)d_in[9];
  const float* be1    = (const float*)d_in[10];
  const float* m1     = (const float*)d_in[11];
  const float* v1     = (const float*)d_in[12];
  const float* w2     = (const float*)d_in[13];
  const float* b2     = (const float*)d_in[14];
  const float* g2     = (const float*)d_in[15];
  const float* be2    = (const float*)d_in[16];
  const float* m2     = (const float*)d_in[17];
  const float* v2     = (const float*)d_in[18];
  const float* taus   = (const float*)d_in[19];
  float* out = (float*)d_out;
  (void)in_sizes; (void)n_in;

  k_colmax32<<<dim3(NG, En), Cn>>>(w1);
  k_prep2<<<En, Cn>>>(g1, be1, m1, v1, b1, g2, be2, m2, v2, b2, taus);
  k_lif<<<Bn*Cn, HWn>>>(x);
  k_logits_gate<<<Nn, Cn>>>(rw, rb, rgam, rbeta, rmean, rvar);
  float* auxp = (out_size > OUT_MAIN) ? (out + OUT_MAIN) : nullptr;
  k_aux<<<1, Nn>>>(auxp);
  k_expert<<<(Nn*28)/8, 256>>>(x, taus, w1, b1, g1, be1, m1, v1, w2, out);
}